// round 11
// baseline (speedup 1.0000x reference)
#include <cuda_runtime.h>
#include <cuda_bf16.h>
#include <cstdint>

// ============================================================================
// FourierKernel via rank-256 factorization (legacy mma.sync; harness targets
// sm_100 base so tcgen05 is unavailable).
//   phi = x @ U, psi = y @ U    (U = rfft basis * gaussian filter, rank 256)
//   out[b] = phi[b] @ psi[b]^T
// Split-bf16: v = hi + lo planes, fp32 acc, 3 passes (HH + HL + LH).
// phi/psi stored PRE-SPLIT so stage 2 has zero convert math.
//
// GEMM: CTA tile 128x128x32, 256 thr, 8 warps of 32x64, TWO CTAs PER SM,
// cp.async double buffer, ONE __syncthreads per k-iteration.
// Loader uses persistent per-thread pointers advanced by constant strides
// (register diet: no per-iteration 64-bit address math under the 128-reg cap).
// Stage 2 launched per-batch (4 launches) so ncu -s 5 captures a GEMM.
//   Stage 1: SPLIT_A=1, OUT_SPLIT=1, grid (2,128,2)  M=16384,N=256,K=512
//   Stage 2: SPLIT_A=0, OUT_SPLIT=0, grid (32,32,1) x4 batches, M=N=4096,K=256
// ============================================================================

#define SEQ   4096
#define BATCH 4
#define RANKC 256
#define FEAT  512
#define MTOT  (BATCH * SEQ)

__device__ __nv_bfloat16 g_UtH[RANKC * FEAT];
__device__ __nv_bfloat16 g_UtL[RANKC * FEAT];
__device__ __nv_bfloat16 g_phiH[MTOT * RANKC];
__device__ __nv_bfloat16 g_phiL[MTOT * RANKC];
__device__ __nv_bfloat16 g_psiH[MTOT * RANKC];
__device__ __nv_bfloat16 g_psiL[MTOT * RANKC];

// per-buffer smem (80B row stride): Ahi[128*80] Alo Bhi Blo
#define A_LO_OFF  10240
#define B_HI_OFF  20480
#define B_LO_OFF  30720
#define BUF_BYTES 40960

// ---------------------------------------------------------------------------
static __device__ __forceinline__ uint32_t smem_u32(const void* p) {
    return (uint32_t)__cvta_generic_to_shared(p);
}
static __device__ __forceinline__ void ldm4(uint32_t& r0, uint32_t& r1,
                                            uint32_t& r2, uint32_t& r3,
                                            uint32_t addr) {
    asm volatile("ldmatrix.sync.aligned.m8n8.x4.shared.b16 {%0,%1,%2,%3}, [%4];"
                 : "=r"(r0), "=r"(r1), "=r"(r2), "=r"(r3) : "r"(addr));
}
static __device__ __forceinline__ void mma_bf16(float* c, const uint32_t* a,
                                                uint32_t b0, uint32_t b1) {
    asm volatile(
        "mma.sync.aligned.m16n8k16.row.col.f32.bf16.bf16.f32 "
        "{%0,%1,%2,%3},{%4,%5,%6,%7},{%8,%9},{%0,%1,%2,%3};"
        : "+f"(c[0]), "+f"(c[1]), "+f"(c[2]), "+f"(c[3])
        : "r"(a[0]), "r"(a[1]), "r"(a[2]), "r"(a[3]), "r"(b0), "r"(b1));
}
static __device__ __forceinline__ void cp16(uint32_t dst, const void* src) {
    asm volatile("cp.async.cg.shared.global [%0], [%1], 16;"
                 :: "r"(dst), "l"(src) : "memory");
}
#define CP_COMMIT() asm volatile("cp.async.commit_group;" ::: "memory")
#define CP_WAIT0()  asm volatile("cp.async.wait_group 0;" ::: "memory")

static __device__ __forceinline__ void split4(float4 v, uint2& hi, uint2& lo) {
    __nv_bfloat162 h01 = __floats2bfloat162_rn(v.x, v.y);
    __nv_bfloat162 h23 = __floats2bfloat162_rn(v.z, v.w);
    float rx = v.x - __bfloat162float(__low2bfloat16(h01));
    float ry = v.y - __bfloat162float(__high2bfloat16(h01));
    float rz = v.z - __bfloat162float(__low2bfloat16(h23));
    float rw = v.w - __bfloat162float(__high2bfloat16(h23));
    __nv_bfloat162 l01 = __floats2bfloat162_rn(rx, ry);
    __nv_bfloat162 l23 = __floats2bfloat162_rn(rz, rw);
    hi.x = *reinterpret_cast<uint32_t*>(&h01);
    hi.y = *reinterpret_cast<uint32_t*>(&h23);
    lo.x = *reinterpret_cast<uint32_t*>(&l01);
    lo.y = *reinterpret_cast<uint32_t*>(&l23);
}

// ---------------------------------------------------------------------------
__global__ void gen_basis_kernel(const float* __restrict__ filt) {
    int idx = blockIdx.x * blockDim.x + threadIdx.x;   // 131072
    int c = idx >> 9, k = idx & 511, r = c >> 1;
    float s = filt[r] * 0.08838834764831843f;          // 1/sqrt(128)
    float ang = (float)((r * k) & 511) * 0.0122718463030851562f;  // 2*pi/512
    float sv, cv;
    sincosf(ang, &sv, &cv);
    float u = (c & 1) ? (-sv * s) : (cv * s);
    __nv_bfloat16 h = __float2bfloat16_rn(u);
    g_UtH[idx] = h;
    g_UtL[idx] = __float2bfloat16_rn(u - __bfloat162float(h));
}

// ---------------------------------------------------------------------------
// GEMM: C (128x128 per CTA) = A(128xK) @ B(128xK)^T, split-bf16 3-pass
// ---------------------------------------------------------------------------
template <bool SPLIT_A, bool OUT_SPLIT>
__global__ __launch_bounds__(256, 2) void gemm_planes(
    const float* __restrict__ Af0, const float* __restrict__ Af1,
    const __nv_bfloat16* __restrict__ AH, const __nv_bfloat16* __restrict__ AL,
    const __nv_bfloat16* __restrict__ BH, const __nv_bfloat16* __restrict__ BL,
    float* __restrict__ Cf,
    __nv_bfloat16* __restrict__ CH0, __nv_bfloat16* __restrict__ CL0,
    __nv_bfloat16* __restrict__ CH1, __nv_bfloat16* __restrict__ CL1,
    int lda, int ldb, int ldc, int K) {
    extern __shared__ __align__(16) char dyn[];
    const uint32_t smemB = smem_u32(dyn);

    const int tid  = threadIdx.x, lane = tid & 31, wid = tid >> 5;
    const int warpM = wid >> 1;          // 0..3  (32-row slices)
    const int warpN = wid & 1;           // 0..1  (64-col slices)
    const int group = lane >> 2;         // 0..7
    const int tig   = lane & 3;          // 0..3
    const int z = blockIdx.z;

    const float* Afp = nullptr;
    long long aRow0, bRow0;
    if constexpr (SPLIT_A) {
        Afp = z ? Af1 : Af0;
        aRow0 = (long long)blockIdx.y * 128;
        bRow0 = (long long)blockIdx.x * 128;
    } else {
        aRow0 = (long long)blockIdx.y * 128;   // pointers pre-offset per batch
        bRow0 = (long long)blockIdx.x * 128;
    }

    // ---- persistent loader state (advance by constant strides per k-tile) ----
    const int r0 = tid >> 2, c4 = tid & 3;        // bf16-plane path
    const int rowA = tid >> 3, vA = tid & 7;      // fp32 path
    const uint32_t dA0 = (uint32_t)(rowA * 80 + vA * 8);    // fp32 hi dst
    const uint32_t dP0 = (uint32_t)(r0 * 80 + c4 * 16);     // plane dst

    const float* srcAf = nullptr;
    const __nv_bfloat16 *srcAH = nullptr, *srcAL = nullptr;
    if constexpr (SPLIT_A) {
        srcAf = Afp + (aRow0 + rowA) * lda + vA * 4;
    } else {
        srcAH = AH + (aRow0 + r0) * lda + c4 * 8;
        srcAL = AL + (aRow0 + r0) * lda + c4 * 8;
    }
    const __nv_bfloat16* srcBH = BH + (bRow0 + r0) * ldb + c4 * 8;
    const __nv_bfloat16* srcBL = BL + (bRow0 + r0) * ldb + c4 * 8;

    auto load_tile = [&](int buf) {
        const uint32_t base = smemB + buf * BUF_BYTES;
        if constexpr (SPLIT_A) {
#pragma unroll
            for (int i = 0; i < 4; ++i) {
                float4 va = *reinterpret_cast<const float4*>(srcAf + i * 32 * lda);
                uint2 hi, lo;
                split4(va, hi, lo);
                uint32_t o = base + dA0 + i * 32 * 80;
                asm volatile("st.shared.v2.b32 [%0], {%1,%2};"
                             :: "r"(o), "r"(hi.x), "r"(hi.y) : "memory");
                asm volatile("st.shared.v2.b32 [%0], {%1,%2};"
                             :: "r"(o + A_LO_OFF), "r"(lo.x), "r"(lo.y) : "memory");
            }
            srcAf += 32;
        } else {
#pragma unroll
            for (int i = 0; i < 2; ++i) {
                cp16(base + dP0 + i * 64 * 80, srcAH + i * 64 * lda);
                cp16(base + A_LO_OFF + dP0 + i * 64 * 80, srcAL + i * 64 * lda);
            }
            srcAH += 32; srcAL += 32;
        }
#pragma unroll
        for (int i = 0; i < 2; ++i) {
            cp16(base + B_HI_OFF + dP0 + i * 64 * 80, srcBH + i * 64 * ldb);
            cp16(base + B_LO_OFF + dP0 + i * 64 * 80, srcBL + i * 64 * ldb);
        }
        srcBH += 32; srcBL += 32;
        CP_COMMIT();
    };

    float acc[2][8][4];
#pragma unroll
    for (int mt = 0; mt < 2; ++mt)
#pragma unroll
        for (int j = 0; j < 8; ++j)
#pragma unroll
            for (int q = 0; q < 4; ++q) acc[mt][j][q] = 0.0f;

    const int ldr   = lane & 15;
    const int ldoff = ((lane >> 4) << 4);
    const int nT = K >> 5;

    load_tile(0);

    for (int kt = 0; kt < nT; ++kt) {
        const int buf = kt & 1;
        CP_WAIT0();
        __syncthreads();
        // prefetch next tile into the other buffer; overlaps compute below
        if (kt + 1 < nT) load_tile(buf ^ 1);

        const uint32_t aHi = smemB + buf * BUF_BYTES;
        const uint32_t aLo = aHi + A_LO_OFF;
        const uint32_t bHi = aHi + B_HI_OFF;
        const uint32_t bLo = aHi + B_LO_OFF;

#pragma unroll
        for (int s = 0; s < 2; ++s) {
            uint32_t aH[2][4], aL[2][4];
#pragma unroll
            for (int mt = 0; mt < 2; ++mt) {
                uint32_t off = (uint32_t)((warpM * 32 + mt * 16 + ldr) * 80 + s * 32 + ldoff);
                ldm4(aH[mt][0], aH[mt][1], aH[mt][2], aH[mt][3], aHi + off);
                ldm4(aL[mt][0], aL[mt][1], aL[mt][2], aL[mt][3], aLo + off);
            }
#pragma unroll
            for (int jp = 0; jp < 4; ++jp) {
                uint32_t off = (uint32_t)((warpN * 64 + jp * 16 + ldr) * 80 + s * 32 + ldoff);
                uint32_t h0, h1, h2, h3, l0, l1, l2, l3;
                ldm4(h0, h1, h2, h3, bHi + off);
                ldm4(l0, l1, l2, l3, bLo + off);
#pragma unroll
                for (int mt = 0; mt < 2; ++mt) {
                    mma_bf16(acc[mt][2 * jp],     aH[mt], h0, h2);  // hi*hi
                    mma_bf16(acc[mt][2 * jp + 1], aH[mt], h1, h3);
                    mma_bf16(acc[mt][2 * jp],     aH[mt], l0, l2);  // hi*lo
                    mma_bf16(acc[mt][2 * jp + 1], aH[mt], l1, l3);
                    mma_bf16(acc[mt][2 * jp],     aL[mt], h0, h2);  // lo*hi
                    mma_bf16(acc[mt][2 * jp + 1], aL[mt], h1, h3);
                }
            }
        }
    }

    // ---- epilogue ----
    if constexpr (!OUT_SPLIT) {
#pragma unroll
        for (int mt = 0; mt < 2; ++mt)
#pragma unroll
            for (int j = 0; j < 8; ++j) {
                int r = blockIdx.y * 128 + warpM * 32 + mt * 16 + group;
                int c = blockIdx.x * 128 + warpN * 64 + j * 8 + tig * 2;
                *reinterpret_cast<float2*>(Cf + (long long)r * ldc + c) =
                    make_float2(acc[mt][j][0], acc[mt][j][1]);
                *reinterpret_cast<float2*>(Cf + (long long)(r + 8) * ldc + c) =
                    make_float2(acc[mt][j][2], acc[mt][j][3]);
            }
    } else {
        __nv_bfloat16* cH = z ? CH1 : CH0;
        __nv_bfloat16* cL = z ? CL1 : CL0;
#pragma unroll
        for (int mt = 0; mt < 2; ++mt)
#pragma unroll
            for (int j = 0; j < 8; ++j) {
                int r = blockIdx.y * 128 + warpM * 32 + mt * 16 + group;
                int c = blockIdx.x * 128 + warpN * 64 + j * 8 + tig * 2;
#pragma unroll
                for (int half = 0; half < 2; ++half) {
                    float f0 = acc[mt][j][2 * half];
                    float f1 = acc[mt][j][2 * half + 1];
                    __nv_bfloat162 hp = __floats2bfloat162_rn(f0, f1);
                    float l0 = f0 - __bfloat162float(__low2bfloat16(hp));
                    float l1 = f1 - __bfloat162float(__high2bfloat16(hp));
                    __nv_bfloat162 lp = __floats2bfloat162_rn(l0, l1);
                    size_t go = (size_t)(r + half * 8) * (size_t)ldc + c;
                    *reinterpret_cast<uint32_t*>(cH + go) =
                        *reinterpret_cast<uint32_t*>(&hp);
                    *reinterpret_cast<uint32_t*>(cL + go) =
                        *reinterpret_cast<uint32_t*>(&lp);
                }
            }
    }
}

// ---------------------------------------------------------------------------
extern "C" void kernel_launch(void* const* d_in, const int* in_sizes, int n_in,
                              void* d_out, int out_size) {
    const float* x    = (const float*)d_in[0];   // (4, 4096, 512)
    const float* y    = (const float*)d_in[1];   // (4, 4096, 512)
    const float* filt = (const float*)d_in[2];   // (128,)
    float* out = (float*)d_out;                  // (4, 4096, 4096)

    __nv_bfloat16 *utH, *utL, *phH, *phL, *psH, *psL;
    cudaGetSymbolAddress((void**)&utH, g_UtH);
    cudaGetSymbolAddress((void**)&utL, g_UtL);
    cudaGetSymbolAddress((void**)&phH, g_phiH);
    cudaGetSymbolAddress((void**)&phL, g_phiL);
    cudaGetSymbolAddress((void**)&psH, g_psiH);
    cudaGetSymbolAddress((void**)&psL, g_psiL);

    const int SMEM = 2 * BUF_BYTES;   // 81920 -> 2 CTAs/SM
    cudaFuncSetAttribute(gemm_planes<true, true>,
                         cudaFuncAttributeMaxDynamicSharedMemorySize, SMEM);
    cudaFuncSetAttribute(gemm_planes<false, false>,
                         cudaFuncAttributeMaxDynamicSharedMemorySize, SMEM);

    // 1) basis planes
    gen_basis_kernel<<<512, 256>>>(filt);

    // 2) phi/psi planes: z=0 -> x, z=1 -> y.  M=16384, N=256, K=512
    gemm_planes<true, true><<<dim3(2, 128, 2), 256, SMEM>>>(
        x, y, nullptr, nullptr, utH, utL,
        nullptr, phH, phL, psH, psL,
        FEAT, FEAT, RANKC, FEAT);

    // 3) out[b] = phi[b] @ psi[b]^T, one launch per batch (ncu -s 5 lands on a
    //    GEMM launch). M=N=4096, K=256.
    for (int b = 0; b < BATCH; ++b) {
        gemm_planes<false, false><<<dim3(32, 32, 1), 256, SMEM>>>(
            nullptr, nullptr,
            phH + (long long)b * SEQ * RANKC, phL + (long long)b * SEQ * RANKC,
            psH + (long long)b * SEQ * RANKC, psL + (long long)b * SEQ * RANKC,
            out + (long long)b * SEQ * SEQ,
            nullptr, nullptr, nullptr, nullptr,
            RANKC, RANKC, SEQ, RANKC);
    }
}